// round 4
// baseline (speedup 1.0000x reference)
#include <cuda_runtime.h>
#include <cstdint>

#define CDIM 128
#define HW   144
#define NB   64
#define RIN  20736
#define N1   5184
#define N2   1296
#define N3   324

// ---------------- scratch (device globals; no allocation allowed) -------------
__device__ float g_inv1[NB*HW];
__device__ float g_inv2[NB*HW];
__device__ float g_act0[(size_t)NB*RIN];
__device__ float g_act1[(size_t)NB*N1];
__device__ float g_act2[(size_t)NB*N2];
__device__ float g_act3[(size_t)NB*N3];
__device__ float g_part[(size_t)25*NB*N1];   // 25 splits max (L1)

// round fp32 -> tf32 (RNA), kept in fp32 bits. Activations only (cheap).
__device__ __forceinline__ float tf32_rna(float x){
  unsigned r; asm("cvt.rna.tf32.f32 %0, %1;" : "=r"(r) : "f"(x));
  return __uint_as_float(r);
}
// compensate mean truncation shrink of W operand in the next tf32 GEMM
#define COMP 1.00035f

// k-interleave permutation within each aligned 16-group: slot = 4*(c%4) + (c%16)/4
__device__ __forceinline__ int kperm(int c){
  return (c & ~15) | (((c & 3) << 2) | ((c >> 2) & 3));
}

// ---------------- 1) inverse channel norms ------------------------------------
template<int WHICH>
__global__ void norm_kernel(const float* __restrict__ x){
  int t = blockIdx.x*blockDim.x + threadIdx.x;
  if (t >= NB*HW) return;
  int n = t / HW, ij = t % HW;
  const float* p = x + (size_t)n*CDIM*HW + ij;
  float s = 0.f;
#pragma unroll 8
  for (int c = 0; c < CDIM; c++){
    float a = p[(size_t)c*HW];
    s += a*a;
  }
  if (WHICH == 0) g_inv1[t] = rsqrtf(s);
  else            g_inv2[t] = rsqrtf(s);
}

// ---------------- 2) correlation (writes k-interleaved act0) -------------------
__global__ void corr_kernel(const float* __restrict__ x1, const float* __restrict__ x2){
  __shared__ float s2t[CDIM][48];
  __shared__ float s1t[CDIM][48];
  int kt = blockIdx.x, jt = blockIdx.y, n = blockIdx.z;
  int tx = threadIdx.x, ty = threadIdx.y;
  int tid = ty*16 + tx;
  const float* xb2 = x2 + (size_t)n*CDIM*HW + kt*48;
  const float* xb1 = x1 + (size_t)n*CDIM*HW + jt*48;
  const float* i2 = g_inv2 + n*HW + kt*48;
  const float* i1 = g_inv1 + n*HW + jt*48;
  for (int idx = tid; idx < CDIM*48; idx += 256){
    int c = idx/48, q = idx%48;
    s2t[c][q] = xb2[(size_t)c*HW + q] * i2[q];
    s1t[c][q] = xb1[(size_t)c*HW + q] * i1[q];
  }
  __syncthreads();
  float acc[3][3] = {};
#pragma unroll 4
  for (int c = 0; c < CDIM; c++){
    float a0 = s1t[c][tx], a1 = s1t[c][tx+16], a2 = s1t[c][tx+32];
    float b0 = s2t[c][ty], b1 = s2t[c][ty+16], b2 = s2t[c][ty+32];
    acc[0][0] += b0*a0; acc[0][1] += b0*a1; acc[0][2] += b0*a2;
    acc[1][0] += b1*a0; acc[1][1] += b1*a1; acc[1][2] += b1*a2;
    acc[2][0] += b2*a0; acc[2][1] += b2*a1; acc[2][2] += b2*a2;
  }
  float* ob = g_act0 + (size_t)n*RIN;
#pragma unroll
  for (int v = 0; v < 3; v++)
#pragma unroll
    for (int u = 0; u < 3; u++){
      int k  = kt*48 + ty + 16*v;
      int ij = jt*48 + tx + 16*u;
      ob[kperm(k*HW + ij)] = tf32_rna(acc[v][u]*COMP);
    }
}

// ---------------- tf32 warp-MMA GEMM: C_part[sp] = A[64,K] @ W[K,N] ------------
__device__ __forceinline__ void cpa16(uint32_t sdst, const void* gsrc){
  asm volatile("cp.async.cg.shared.global [%0], [%1], 16;" :: "r"(sdst), "l"(gsrc));
}

#define STAGES 5
#define AS_BYTES (64*16*4)     // 4096, no pad (conflict-free for float4 frags)
#define BS_BYTES (16*200*4)    // 12800
#define SMEM_BYTES (STAGES*(AS_BYTES+BS_BYTES))   // 84480

template<int LAYER>
__global__ __launch_bounds__(384, 2) void gemm_tf32(const float* __restrict__ W){
  constexpr int N   = (LAYER==0) ? N1  : (LAYER==1) ? N2 : N3;
  constexpr int K   = (LAYER==0) ? RIN : (LAYER==1) ? N1 : N2;
  constexpr int KCH = (LAYER==0) ? 944 : (LAYER==1) ? 208 : 64;  // multiples of 16
  const float* __restrict__ A = (LAYER==0) ? g_act0 : (LAYER==1) ? g_act1 : g_act2;

  extern __shared__ char smem_raw[];
  float (*As)[64][16]  = reinterpret_cast<float(*)[64][16]>(smem_raw);
  float (*Bs)[16][200] = reinterpret_cast<float(*)[16][200]>(smem_raw + STAGES*AS_BYTES);

  int n0 = blockIdx.x*192;
  int sp = blockIdx.y;
  int k0 = sp*KCH;
  int kend = min(k0 + KCH, K);
  int nit = (kend - k0 + 15)/16;

  int tid = threadIdx.x;
  int warp = tid>>5, lane = tid&31;
  int wm = warp&1, wn = warp>>1;      // 2 x 6 warp grid, warp tile 32x32
  int gid = lane>>2, tig = lane&3;

  int arow = (tid&255)>>2, ach = tid&3;   // A tile: first 256 threads, 64 rows x 4 chunks
  const float* asrc = A + (size_t)arow*K + ach*4;
  int brow[2], bch[2];
#pragma unroll
  for (int j = 0; j < 2; j++){        // B tile: 16 rows x 48 chunks = 768 = 2*384
    int idx = tid + 384*j;
    brow[j] = idx/48; bch[j] = idx%48;
  }

  auto load_stage = [&](int buf, int kb){
    if (tid < 256){
      int kg = kb + ach*4;
      float* d = &As[buf][arow][ach*4];
      if (kg < kend) cpa16((uint32_t)__cvta_generic_to_shared(d), asrc + kb);
      else *(float4*)d = make_float4(0.f,0.f,0.f,0.f);
    }
#pragma unroll
    for (int j = 0; j < 2; j++){
      int kg = kb + brow[j];
      int nc = n0 + bch[j]*4;
      float* d = &Bs[buf][brow[j]][bch[j]*4];
      if (kg < kend && nc < N)
        cpa16((uint32_t)__cvta_generic_to_shared(d), W + (size_t)kg*N + nc);
      else *(float4*)d = make_float4(0.f,0.f,0.f,0.f);
    }
    asm volatile("cp.async.commit_group;" ::: "memory");
  };

  float acc[2][4][4];
#pragma unroll
  for (int i=0;i<2;i++)
#pragma unroll
    for (int j=0;j<4;j++)
#pragma unroll
      for (int r=0;r<4;r++) acc[i][j][r] = 0.f;

  // prologue: fill STAGES-1 stages
  load_stage(0, k0);
  load_stage(1, k0 + 16);
  load_stage(2, k0 + 32);
  load_stage(3, k0 + 48);

  int rbase = wm*32 + gid;
  int buf = 0, lbuf = STAGES-1;
  for (int it = 0; it < nit; it++){
    asm volatile("cp.async.wait_group %0;" :: "n"(STAGES-2) : "memory");
    __syncthreads();
    if (it + STAGES-1 < nit) load_stage(lbuf, k0 + (it + STAGES-1)*16);
    else asm volatile("cp.async.commit_group;" ::: "memory");
    if (++lbuf == STAGES) lbuf = 0;

    // A fragments: 4 vectorized LDS.128 (k-interleaved layout)
    float4 v0 = *(const float4*)&As[buf][rbase   ][4*tig];
    float4 v1 = *(const float4*)&As[buf][rbase+8 ][4*tig];
    float4 v2 = *(const float4*)&As[buf][rbase+16][4*tig];
    float4 v3 = *(const float4*)&As[buf][rbase+24][4*tig];
    // B fragments: 16 scalar LDS (rows tig, tig+4, tig+8, tig+12)
    uint32_t b[4][4];
#pragma unroll
    for (int jj = 0; jj < 4; jj++){
      int nc = wn*32 + jj*8 + gid;
      b[jj][0] = __float_as_uint(Bs[buf][tig   ][nc]);
      b[jj][1] = __float_as_uint(Bs[buf][tig+4 ][nc]);
      b[jj][2] = __float_as_uint(Bs[buf][tig+8 ][nc]);
      b[jj][3] = __float_as_uint(Bs[buf][tig+12][nc]);
    }
#define MMA(ac, A0,A1,A2,A3, B0,B1) \
    asm volatile("mma.sync.aligned.m16n8k8.row.col.f32.tf32.tf32.f32 " \
      "{%0,%1,%2,%3},{%4,%5,%6,%7},{%8,%9},{%0,%1,%2,%3};" \
      : "+f"(ac[0]), "+f"(ac[1]), "+f"(ac[2]), "+f"(ac[3]) \
      : "r"(__float_as_uint(A0)), "r"(__float_as_uint(A1)), \
        "r"(__float_as_uint(A2)), "r"(__float_as_uint(A3)), \
        "r"(B0), "r"(B1))
#pragma unroll
    for (int jj = 0; jj < 4; jj++){
      MMA(acc[0][jj], v0.x, v1.x, v0.y, v1.y, b[jj][0], b[jj][1]);  // kk=0, i=0
      MMA(acc[1][jj], v2.x, v3.x, v2.y, v3.y, b[jj][0], b[jj][1]);  // kk=0, i=1
      MMA(acc[0][jj], v0.z, v1.z, v0.w, v1.w, b[jj][2], b[jj][3]);  // kk=8, i=0
      MMA(acc[1][jj], v2.z, v3.z, v2.w, v3.w, b[jj][2], b[jj][3]);  // kk=8, i=1
    }
#undef MMA
    if (++buf == STAGES) buf = 0;
  }

  float* Crow = g_part + (size_t)sp*NB*N;
#pragma unroll
  for (int i = 0; i < 2; i++){
    int m0 = wm*32 + i*16 + gid;
#pragma unroll
    for (int jj = 0; jj < 4; jj++){
      int n = n0 + wn*32 + jj*8 + tig*2;
      if (n < N){
        *(float2*)&Crow[(size_t)m0*N + n]     = make_float2(acc[i][jj][0], acc[i][jj][1]);
        *(float2*)&Crow[(size_t)(m0+8)*N + n] = make_float2(acc[i][jj][2], acc[i][jj][3]);
      }
    }
  }
}

// ---------------- split-K reduce + bias + activation ---------------------------
// LAYER<2 writes k-interleaved layout (feeds next gemm's A operand).
template<int LAYER>
__global__ void epi_kernel(const float* __restrict__ bias){
  constexpr int N      = (LAYER==0) ? N1 : (LAYER==1) ? N2 : N3;
  constexpr int SPLITS = (LAYER==0) ? 22 : (LAYER==1) ? 25 : 21;
  float* __restrict__ out = (LAYER==0) ? g_act1 : (LAYER==1) ? g_act2 : g_act3;
  int idx = (blockIdx.x*256 + threadIdx.x)*4;
  if (idx >= NB*N) return;
  int n = idx % N;        // N % 16 == 0, lanes map to n..n+3, n%4==0
  float4 s = make_float4(0.f,0.f,0.f,0.f);
#pragma unroll
  for (int sp = 0; sp < SPLITS; sp++){
    float4 p = *(const float4*)&g_part[(size_t)sp*NB*N + idx];
    s.x += p.x; s.y += p.y; s.z += p.z; s.w += p.w;
  }
  float4 bv = *(const float4*)&bias[n];
  s.x += bv.x; s.y += bv.y; s.z += bv.z; s.w += bv.w;
  if (LAYER < 2){
    int base = idx & ~15;
    int q = (idx >> 2) & 3;
    out[base + q]      = tf32_rna(fmaxf(s.x,0.f)*COMP);
    out[base + 4 + q]  = tf32_rna(fmaxf(s.y,0.f)*COMP);
    out[base + 8 + q]  = tf32_rna(fmaxf(s.z,0.f)*COMP);
    out[base + 12 + q] = tf32_rna(fmaxf(s.w,0.f)*COMP);
  } else {
    float4 o;
    o.x = tanhf(s.x); o.y = tanhf(s.y); o.z = tanhf(s.z); o.w = tanhf(s.w);
    *(float4*)&out[idx] = o;
  }
}

// ---------------- final linear [64,324]->[64,8] + ones -> [64,3,3] -------------
__global__ void final_kernel(const float* __restrict__ w4, const float* __restrict__ b4,
                             float* __restrict__ out){
  int t = threadIdx.x;
  if (t >= 512) return;
  int m = t>>3, n = t&7;
  const float* a = g_act3 + (size_t)m*N3;
  float acc = b4[n];
#pragma unroll 4
  for (int k = 0; k < N3; k++) acc += a[k]*w4[k*8 + n];
  out[m*9 + n] = acc;
  if (n == 0) out[m*9 + 8] = 1.0f;
}

// ---------------- launch --------------------------------------------------------
extern "C" void kernel_launch(void* const* d_in, const int* in_sizes, int n_in,
                              void* d_out, int out_size){
  const float* x1 = (const float*)d_in[0];
  const float* x2 = (const float*)d_in[1];
  const float* w1 = (const float*)d_in[2];
  const float* b1 = (const float*)d_in[3];
  const float* w2 = (const float*)d_in[4];
  const float* b2 = (const float*)d_in[5];
  const float* w3 = (const float*)d_in[6];
  const float* b3 = (const float*)d_in[7];
  const float* w4 = (const float*)d_in[8];
  const float* b4 = (const float*)d_in[9];
  float* out = (float*)d_out;

  cudaFuncSetAttribute(gemm_tf32<0>, cudaFuncAttributeMaxDynamicSharedMemorySize, SMEM_BYTES);
  cudaFuncSetAttribute(gemm_tf32<1>, cudaFuncAttributeMaxDynamicSharedMemorySize, SMEM_BYTES);
  cudaFuncSetAttribute(gemm_tf32<2>, cudaFuncAttributeMaxDynamicSharedMemorySize, SMEM_BYTES);

  norm_kernel<0><<<36, 256>>>(x1);                 // idx 0
  norm_kernel<1><<<36, 256>>>(x2);                 // idx 1
  corr_kernel<<<dim3(3,3,64), dim3(16,16)>>>(x1, x2);  // idx 2

  gemm_tf32<0><<<dim3(27, 22), 384, SMEM_BYTES>>>(w1); // idx 3: 594 CTAs = 2.007 waves
  epi_kernel<0><<<324, 256>>>(b1);

  gemm_tf32<1><<<dim3(7, 25), 384, SMEM_BYTES>>>(w2);  // 5184 -> 1296, KCH=208
  epi_kernel<1><<<81, 256>>>(b2);

  gemm_tf32<2><<<dim3(2, 21), 384, SMEM_BYTES>>>(w3);  // 1296 -> 324, KCH=64
  epi_kernel<2><<<21, 256>>>(b3);

  final_kernel<<<1, 512>>>(w4, b4, out);               // 324 -> 8, append ones
}

// round 5
// speedup vs baseline: 1.3768x; 1.3768x over previous
#include <cuda_runtime.h>
#include <cstdint>

#define CDIM 128
#define HW   144
#define NB   64
#define RIN  20736
#define N1   5184
#define N2   1296
#define N3   324

// ---------------- scratch (device globals; no allocation allowed) -------------
__device__ float g_act0[(size_t)NB*RIN];
__device__ float g_act1[(size_t)NB*N1];
__device__ float g_act2[(size_t)NB*N2];
__device__ float g_act3[(size_t)NB*N3];
__device__ float g_part[(size_t)25*NB*N1];   // 25 splits max

// round fp32 -> tf32 (RNA), kept in fp32 bits. Activations only (cheap).
__device__ __forceinline__ float tf32_rna(float x){
  unsigned r; asm("cvt.rna.tf32.f32 %0, %1;" : "=r"(r) : "f"(x));
  return __uint_as_float(r);
}
// compensate mean truncation shrink of W operand in the next tf32 GEMM
#define COMP 1.00035f

// ---------------- correlation with fused L2 norms -----------------------------
// act0[n, k*144+ij] = (sum_c x1[c,ij]x2[c,k]) * inv1[ij] * inv2[k]
__global__ void corr_kernel(const float* __restrict__ x1, const float* __restrict__ x2){
  __shared__ float s2t[CDIM][48];
  __shared__ float s1t[CDIM][48];
  __shared__ float inv1s[48], inv2s[48];
  int kt = blockIdx.x, jt = blockIdx.y, n = blockIdx.z;
  int tx = threadIdx.x, ty = threadIdx.y;
  int tid = ty*16 + tx;
  const float* xb2 = x2 + (size_t)n*CDIM*HW + kt*48;
  const float* xb1 = x1 + (size_t)n*CDIM*HW + jt*48;
  for (int idx = tid; idx < CDIM*48; idx += 256){
    int c = idx/48, q = idx%48;
    s2t[c][q] = xb2[(size_t)c*HW + q];
    s1t[c][q] = xb1[(size_t)c*HW + q];
  }
  __syncthreads();
  // fused norm: column sums of squares (96 threads, one column each)
  if (tid < 96){
    int q = tid % 48;
    float s = 0.f;
    if (tid < 48){
#pragma unroll 8
      for (int c = 0; c < CDIM; c++){ float a = s1t[c][q]; s += a*a; }
      inv1s[q] = rsqrtf(s);
    } else {
#pragma unroll 8
      for (int c = 0; c < CDIM; c++){ float a = s2t[c][q]; s += a*a; }
      inv2s[q] = rsqrtf(s);
    }
  }
  float acc[3][3] = {};
#pragma unroll 4
  for (int c = 0; c < CDIM; c++){
    float a0 = s1t[c][tx], a1 = s1t[c][tx+16], a2 = s1t[c][tx+32];
    float b0 = s2t[c][ty], b1 = s2t[c][ty+16], b2 = s2t[c][ty+32];
    acc[0][0] += b0*a0; acc[0][1] += b0*a1; acc[0][2] += b0*a2;
    acc[1][0] += b1*a0; acc[1][1] += b1*a1; acc[1][2] += b1*a2;
    acc[2][0] += b2*a0; acc[2][1] += b2*a1; acc[2][2] += b2*a2;
  }
  __syncthreads();   // inv1s/inv2s ready
  float* ob = g_act0 + (size_t)n*RIN;
#pragma unroll
  for (int v = 0; v < 3; v++)
#pragma unroll
    for (int u = 0; u < 3; u++){
      int kl = ty + 16*v, il = tx + 16*u;
      int k  = kt*48 + kl;
      int ij = jt*48 + il;
      ob[(size_t)k*HW + ij] = tf32_rna(acc[v][u]*inv1s[il]*inv2s[kl]*COMP);
    }
}

// ---------------- tf32 warp-MMA GEMM: C_part[sp] = A[64,K] @ W[K,N] ------------
__device__ __forceinline__ void cpa16(uint32_t sdst, const void* gsrc){
  asm volatile("cp.async.cg.shared.global [%0], [%1], 16;" :: "r"(sdst), "l"(gsrc));
}

#define STAGES 6
#define AS_BYTES (64*20*4)     // 5120
#define BS_BYTES (16*200*4)    // 12800
#define SMEM_BYTES (STAGES*(AS_BYTES+BS_BYTES))   // 107520

template<int LAYER>
__global__ __launch_bounds__(256) void gemm_tf32(const float* __restrict__ W){
  constexpr int N   = (LAYER==0) ? N1  : (LAYER==1) ? N2 : N3;
  constexpr int K   = (LAYER==0) ? RIN : (LAYER==1) ? N1 : N2;
  constexpr int KCH = (LAYER==0) ? 944 : (LAYER==1) ? 208 : 64;
  const float* __restrict__ A = (LAYER==0) ? g_act0 : (LAYER==1) ? g_act1 : g_act2;

  extern __shared__ char smem_raw[];
  float (*As)[64][20]  = reinterpret_cast<float(*)[64][20]>(smem_raw);
  float (*Bs)[16][200] = reinterpret_cast<float(*)[16][200]>(smem_raw + STAGES*AS_BYTES);

  int n0 = blockIdx.x*192;
  int sp = blockIdx.y;
  int k0 = sp*KCH;
  int kend = min(k0 + KCH, K);
  int nit = (kend - k0 + 15)/16;

  int tid = threadIdx.x;
  int warp = tid>>5, lane = tid&31;
  int wm = warp&1, wn = warp>>1;      // 2 x 4 warp grid, warp tile 32x48
  int gid = lane>>2, tig = lane&3;

  int arow = tid>>2, ach = tid&3;     // A tile: 64 rows x 4 chunks of 16B
  const float* asrc = A + (size_t)arow*K + ach*4;
  int brow[3], bch[3];
#pragma unroll
  for (int j = 0; j < 3; j++){        // B tile: 16 rows x 48 chunks of 16B
    int idx = tid + 256*j;
    brow[j] = idx/48; bch[j] = idx%48;
  }

  auto load_stage = [&](int buf, int kb){
    {
      int kg = kb + ach*4;
      float* d = &As[buf][arow][ach*4];
      if (kg < kend) cpa16((uint32_t)__cvta_generic_to_shared(d), asrc + kb);
      else *(float4*)d = make_float4(0.f,0.f,0.f,0.f);
    }
#pragma unroll
    for (int j = 0; j < 3; j++){
      int kg = kb + brow[j];
      int nc = n0 + bch[j]*4;
      float* d = &Bs[buf][brow[j]][bch[j]*4];
      if (kg < kend && nc < N)
        cpa16((uint32_t)__cvta_generic_to_shared(d), W + (size_t)kg*N + nc);
      else *(float4*)d = make_float4(0.f,0.f,0.f,0.f);
    }
    asm volatile("cp.async.commit_group;" ::: "memory");
  };

  float acc[2][6][4];
#pragma unroll
  for (int i=0;i<2;i++)
#pragma unroll
    for (int j=0;j<6;j++)
#pragma unroll
      for (int r=0;r<4;r++) acc[i][j][r] = 0.f;

  // prologue: fill STAGES-1 stages (beyond-kend stages write zeros, harmless)
  load_stage(0, k0);
  load_stage(1, k0 + 16);
  load_stage(2, k0 + 32);
  load_stage(3, k0 + 48);
  load_stage(4, k0 + 64);

  int buf = 0, lbuf = STAGES-1;
  for (int it = 0; it < nit; it++){
    asm volatile("cp.async.wait_group %0;" :: "n"(STAGES-2) : "memory");
    __syncthreads();
    if (it + STAGES-1 < nit) load_stage(lbuf, k0 + (it + STAGES-1)*16);
    else asm volatile("cp.async.commit_group;" ::: "memory");  // keep group count in lockstep
    if (++lbuf == STAGES) lbuf = 0;
#pragma unroll
    for (int kk = 0; kk < 16; kk += 8){
      uint32_t a[2][4];
#pragma unroll
      for (int i = 0; i < 2; i++){
        int mr = wm*32 + i*16 + gid;
        a[i][0] = __float_as_uint(As[buf][mr  ][kk+tig  ]);
        a[i][1] = __float_as_uint(As[buf][mr+8][kk+tig  ]);
        a[i][2] = __float_as_uint(As[buf][mr  ][kk+tig+4]);
        a[i][3] = __float_as_uint(As[buf][mr+8][kk+tig+4]);
      }
      uint32_t b[6][2];
#pragma unroll
      for (int j = 0; j < 6; j++){
        int nc = wn*48 + j*8 + gid;
        b[j][0] = __float_as_uint(Bs[buf][kk+tig  ][nc]);
        b[j][1] = __float_as_uint(Bs[buf][kk+tig+4][nc]);
      }
#pragma unroll
      for (int i = 0; i < 2; i++)
#pragma unroll
        for (int j = 0; j < 6; j++)
          asm volatile(
            "mma.sync.aligned.m16n8k8.row.col.f32.tf32.tf32.f32 "
            "{%0,%1,%2,%3},{%4,%5,%6,%7},{%8,%9},{%0,%1,%2,%3};"
            : "+f"(acc[i][j][0]), "+f"(acc[i][j][1]),
              "+f"(acc[i][j][2]), "+f"(acc[i][j][3])
            : "r"(a[i][0]), "r"(a[i][1]), "r"(a[i][2]), "r"(a[i][3]),
              "r"(b[j][0]), "r"(b[j][1]));
    }
    if (++buf == STAGES) buf = 0;
  }

  float* Crow = g_part + (size_t)sp*NB*N;
#pragma unroll
  for (int i = 0; i < 2; i++){
    int m0 = wm*32 + i*16 + gid;
#pragma unroll
    for (int j = 0; j < 6; j++){
      int n = n0 + wn*48 + j*8 + tig*2;
      if (n < N){
        *(float2*)&Crow[(size_t)m0*N + n]     = make_float2(acc[i][j][0], acc[i][j][1]);
        *(float2*)&Crow[(size_t)(m0+8)*N + n] = make_float2(acc[i][j][2], acc[i][j][3]);
      }
    }
  }
}

// ---------------- split-K reduce + bias + activation (float4) ------------------
template<int LAYER>
__global__ void epi_kernel(const float* __restrict__ bias){
  constexpr int N      = (LAYER==0) ? N1 : (LAYER==1) ? N2 : N3;
  constexpr int SPLITS = (LAYER==0) ? 22 : (LAYER==1) ? 25 : 21;
  float* __restrict__ out = (LAYER==0) ? g_act1 : (LAYER==1) ? g_act2 : g_act3;
  int idx = (blockIdx.x*256 + threadIdx.x)*4;
  if (idx >= NB*N) return;
  int n = idx % N;        // N % 4 == 0, lanes map to n..n+3
  float4 s = make_float4(0.f,0.f,0.f,0.f);
#pragma unroll
  for (int sp = 0; sp < SPLITS; sp++){
    float4 p = *(const float4*)&g_part[(size_t)sp*NB*N + idx];
    s.x += p.x; s.y += p.y; s.z += p.z; s.w += p.w;
  }
  float4 bv = *(const float4*)&bias[n];
  s.x += bv.x; s.y += bv.y; s.z += bv.z; s.w += bv.w;
  float4 o;
  if (LAYER < 2){
    o.x = tf32_rna(fmaxf(s.x,0.f)*COMP); o.y = tf32_rna(fmaxf(s.y,0.f)*COMP);
    o.z = tf32_rna(fmaxf(s.z,0.f)*COMP); o.w = tf32_rna(fmaxf(s.w,0.f)*COMP);
  } else {
    o.x = tanhf(s.x); o.y = tanhf(s.y); o.z = tanhf(s.z); o.w = tanhf(s.w);
  }
  *(float4*)&out[idx] = o;
}

// ---------------- final linear [64,324]->[64,8] + ones -> [64,3,3] -------------
// one CTA per batch row; 256 threads = 8 n x 32 k-groups; smem tree reduce
__global__ void final_kernel(const float* __restrict__ w4, const float* __restrict__ b4,
                             float* __restrict__ out){
  __shared__ float sm[256];
  int m = blockIdx.x;
  int t = threadIdx.x;
  int n = t & 7, kg = t >> 3;
  const float* a = g_act3 + (size_t)m*N3;
  float s = 0.f;
  for (int k = kg; k < N3; k += 32) s += a[k]*w4[k*8 + n];
  sm[t] = s;
  __syncthreads();
#pragma unroll
  for (int off = 128; off >= 8; off >>= 1){
    if (t < off) sm[t] += sm[t + off];
    __syncthreads();
  }
  if (t < 8) out[m*9 + t] = sm[t] + b4[t];
  if (t == 8) out[m*9 + 8] = 1.0f;
}

// ---------------- launch --------------------------------------------------------
extern "C" void kernel_launch(void* const* d_in, const int* in_sizes, int n_in,
                              void* d_out, int out_size){
  const float* x1 = (const float*)d_in[0];
  const float* x2 = (const float*)d_in[1];
  const float* w1 = (const float*)d_in[2];
  const float* b1 = (const float*)d_in[3];
  const float* w2 = (const float*)d_in[4];
  const float* b2 = (const float*)d_in[5];
  const float* w3 = (const float*)d_in[6];
  const float* b3 = (const float*)d_in[7];
  const float* w4 = (const float*)d_in[8];
  const float* b4 = (const float*)d_in[9];
  float* out = (float*)d_out;

  cudaFuncSetAttribute(gemm_tf32<0>, cudaFuncAttributeMaxDynamicSharedMemorySize, SMEM_BYTES);
  cudaFuncSetAttribute(gemm_tf32<1>, cudaFuncAttributeMaxDynamicSharedMemorySize, SMEM_BYTES);
  cudaFuncSetAttribute(gemm_tf32<2>, cudaFuncAttributeMaxDynamicSharedMemorySize, SMEM_BYTES);

  corr_kernel<<<dim3(3,3,64), dim3(16,16)>>>(x1, x2);  // idx 0 (norms fused)

  gemm_tf32<0><<<dim3(27, 22), 256, SMEM_BYTES>>>(w1); // idx 1: 594 CTAs
  epi_kernel<0><<<324, 256>>>(b1);                     // idx 2

  gemm_tf32<1><<<dim3(7, 25), 256, SMEM_BYTES>>>(w2);  // idx 3 (profiled slot)
  epi_kernel<1><<<81, 256>>>(b2);

  gemm_tf32<2><<<dim3(2, 21), 256, SMEM_BYTES>>>(w3);  // 1296 -> 324
  epi_kernel<2><<<21, 256>>>(b3);

  final_kernel<<<64, 256>>>(w4, b4, out);              // 324 -> 8, append ones
}